// round 13
// baseline (speedup 1.0000x reference)
#include <cuda_runtime.h>
#include <cuda_bf16.h>
#include <cstdint>

#define NB 4
#define NC 64
#define NH 128
#define NW 128
#define NO 64
#define NOFF 18
#define NCK 576
#define HWSZ (NH * NW)

__device__ float g_offsets[NB * NOFF * NH * NW];
__device__ float g_xt[NB * NH * NW * NC];        // NHWC
__device__ unsigned short g_wimg[74752];         // B hi[64][584] + lo[64][584]
__device__ unsigned int g_ctr;                   // dynamic tile counter

// ---- helpers -------------------------------------------------------------
__device__ __forceinline__ unsigned long long dup2(float v) {
    unsigned long long r; asm("mov.b64 %0, {%1, %1};" : "=l"(r) : "f"(v)); return r;
}
__device__ __forceinline__ unsigned long long pack2(float lo, float hi) {
    unsigned long long r; asm("mov.b64 %0, {%1, %2};" : "=l"(r) : "f"(lo), "f"(hi)); return r;
}
__device__ __forceinline__ void unpack2(unsigned long long v, float& lo, float& hi) {
    asm("mov.b64 {%0, %1}, %2;" : "=f"(lo), "=f"(hi) : "l"(v));
}
__device__ __forceinline__ void fma2(unsigned long long& d,
                                     unsigned long long a, unsigned long long b) {
    asm("fma.rn.f32x2 %0, %1, %2, %0;" : "+l"(d) : "l"(a), "l"(b));
}
__device__ __forceinline__ uint32_t smem_u32(const void* p) {
    uint32_t a;
    asm("{ .reg .u64 t; cvta.to.shared.u64 t, %1; cvt.u32.u64 %0, t; }" : "=r"(a) : "l"(p));
    return a;
}
__device__ __forceinline__ uint32_t cvtbf2(float alo, float ahi) {
    uint32_t r; asm("cvt.rn.bf16x2.f32 %0, %1, %2;" : "=r"(r) : "f"(ahi), "f"(alo)); return r;
}
__device__ __forceinline__ void ldsm4(uint32_t* r, uint32_t a) {
    asm volatile("ldmatrix.sync.aligned.m8n8.x4.shared.b16 {%0,%1,%2,%3}, [%4];"
        : "=r"(r[0]), "=r"(r[1]), "=r"(r[2]), "=r"(r[3]) : "r"(a));
}
__device__ __forceinline__ void mma16816(float* c, const uint32_t* a,
                                         uint32_t b0, uint32_t b1) {
    asm volatile("mma.sync.aligned.m16n8k16.row.col.f32.bf16.bf16.f32 "
        "{%0,%1,%2,%3}, {%4,%5,%6,%7}, {%8,%9}, {%0,%1,%2,%3};"
        : "+f"(c[0]), "+f"(c[1]), "+f"(c[2]), "+f"(c[3])
        : "r"(a[0]), "r"(a[1]), "r"(a[2]), "r"(a[3]), "r"(b0), "r"(b1));
}
__device__ __forceinline__ void bar_sync(int id, int cnt) {
    asm volatile("bar.sync %0, %1;" :: "r"(id), "r"(cnt) : "memory");
}

// ---------------------------------------------------------------------------
// Kernel 0: weight -> hi/lo bf16 B images; also resets the tile counter.
// ---------------------------------------------------------------------------
__global__ void wprep_kernel(const float* __restrict__ weight) {
    if (blockIdx.x == 0 && threadIdx.x == 0) g_ctr = 0u;
    int idx = blockIdx.x * 256 + threadIdx.x;
    if (idx < NO * NCK) {
        int o = idx / NCK;
        int r = idx - o * NCK;
        int c = r / 9;
        int k = r - c * 9;
        float v = weight[idx];
        __nv_bfloat16 hb = __float2bfloat16(v);
        __nv_bfloat16 lb = __float2bfloat16(v - __bfloat162float(hb));
        int i16 = o * 584 + k * 64 + c;
        g_wimg[i16] = *(unsigned short*)&hb;
        g_wimg[37376 + i16] = *(unsigned short*)&lb;
    }
}

// ---------------------------------------------------------------------------
// Kernel 0b: NCHW -> NHWC.
// ---------------------------------------------------------------------------
__global__ __launch_bounds__(256) void nhwc_kernel(const float* __restrict__ x) {
    __shared__ float ts[NC * 129];
    int bh = blockIdx.x;
    int b = bh >> 7, h = bh & 127;
    int t = threadIdx.x;
    for (int i = t; i < NC * NW; i += 256) {
        int c = i >> 7, w = i & 127;
        ts[c * 129 + w] = x[((size_t)(b * NC + c) * NH + h) * NW + w];
    }
    __syncthreads();
    for (int i = t; i < NC * NW; i += 256) {
        int w = i >> 6, c = i & 63;
        g_xt[(((size_t)(b * NH + h) * NW) + w) * NC + c] = ts[c * 129 + w];
    }
}

// ---------------------------------------------------------------------------
// Kernel 1: offset conv (f32x2), known good since R2.
// ---------------------------------------------------------------------------
__global__ __launch_bounds__(128) void offsets_kernel(
    const float* __restrict__ x, const float* __restrict__ offw,
    const float* __restrict__ offb)
{
    __shared__ __align__(16) float ws2[9 * NC * 10 * 2];
    int t = threadIdx.x;
    for (int i = t; i < 9 * NC * 10 * 2; i += 128) ws2[i] = 0.f;
    __syncthreads();
    for (int i = t; i < NOFF * NC * 9; i += 128) {
        int kk = i / (NC * 9);
        int rem = i - kk * (NC * 9);
        int c = rem / 9;
        int tap = rem - c * 9;
        ws2[((tap * NC + c) * 10 + (kk >> 1)) * 2 + (kk & 1)] = offw[i];
    }
    int h = blockIdx.x, b = blockIdx.y, w = t;
    unsigned long long acc[9];
#pragma unroll
    for (int j = 0; j < 9; j++) acc[j] = pack2(__ldg(&offb[2 * j]), __ldg(&offb[2 * j + 1]));
    __syncthreads();
    bool ok9[9]; int idx9[9];
#pragma unroll
    for (int dh = 0; dh < 3; dh++)
#pragma unroll
        for (int dw = 0; dw < 3; dw++) {
            int hh = h + dh - 1, ww2 = w + dw - 1;
            ok9[dh * 3 + dw] = (hh >= 0 && hh < NH && ww2 >= 0 && ww2 < NW);
            idx9[dh * 3 + dw] = hh * NW + ww2;
        }
    const float* xb = x + (size_t)b * NC * HWSZ;
    for (int c = 0; c < NC; c++) {
        const float* xc = xb + c * HWSZ;
        float v[9];
#pragma unroll
        for (int k = 0; k < 9; k++) v[k] = ok9[k] ? __ldg(&xc[idx9[k]]) : 0.f;
#pragma unroll
        for (int tap = 0; tap < 9; tap++) {
            unsigned long long vd = dup2(v[tap]);
            const ulonglong2* wq = (const ulonglong2*)&ws2[(tap * NC + c) * 20];
            ulonglong2 q0 = wq[0], q1 = wq[1], q2 = wq[2], q3 = wq[3], q4 = wq[4];
            fma2(acc[0], vd, q0.x); fma2(acc[1], vd, q0.y);
            fma2(acc[2], vd, q1.x); fma2(acc[3], vd, q1.y);
            fma2(acc[4], vd, q2.x); fma2(acc[5], vd, q2.y);
            fma2(acc[6], vd, q3.x); fma2(acc[7], vd, q3.y);
            fma2(acc[8], vd, q4.x);
        }
    }
#pragma unroll
    for (int j = 0; j < 9; j++) {
        float lo, hi; unpack2(acc[j], lo, hi);
        g_offsets[((b * NOFF + 2 * j) * NH + h) * NW + w] = lo;
        g_offsets[((b * NOFF + 2 * j + 1) * NH + h) * NW + w] = hi;
    }
}

// ---------------------------------------------------------------------------
// Kernel 2: HMMA deform. 2 pipelines x 12 warps (768 thr). Pipeline:
// 64-px half-row tile, 4 slots of 32x32 warp tiles x 3 tap-groups.
// Dynamic tile stealing via g_ctr. SMEM: B 149504 | A 2x2x18432 |
// prm 2x3072 | ctl 128 = 229504 B.
// ---------------------------------------------------------------------------
#define SM_A 149504
#define SM_PRM 223232
#define SM_CTL 229376
#define SMEM_SZ 229504

__global__ __launch_bounds__(768, 1) void deform_kernel(
    const float* __restrict__ xt, const float* __restrict__ bias,
    float* __restrict__ out)
{
    extern __shared__ __align__(16) char sm[];
    uint32_t sb = smem_u32(sm);
    int t = threadIdx.x, l = t & 31, wi = t >> 5;   // wi 0..23
    int p = (wi >= 12) ? 1 : 0;
    int wl = wi - p * 12;          // warp in pipeline 0..11
    int tl = t - p * 384;          // thread in pipeline
    int barid = 1 + p;
    int grp = wl >> 2;             // tap group 0..2
    int slot4 = wl & 3;
    int m0 = (slot4 >> 1) * 32;    // 0 or 32 (local px)
    int nq = (slot4 & 1) * 32;     // 0 or 32

    {   // load B images once (all threads)
        const float4* src = (const float4*)g_wimg;
        float4* dst = (float4*)sm;
        for (int i = t; i < 9344; i += 768) dst[i] = src[i];
    }
    __syncthreads();

    uint32_t a_lane = (uint32_t)((l & 15) * 72 + ((l >> 4) << 3));
    uint32_t b_lane = (uint32_t)((nq + (l & 7) + ((l >> 4) << 3)) * 584 + (l & 8));

    char* aregion = sm + SM_A + p * 36864;                     // 2 slots x 18432
    float4* prmF = (float4*)(sm + SM_PRM + p * 3072);          // [2][64]
    ushort4* prmI = (ushort4*)(sm + SM_PRM + p * 3072 + 2048); // [2][64]
    unsigned* ctl = (unsigned*)(sm + SM_CTL) + p * 16;

    for (;;) {
        if (tl == 0) ctl[0] = atomicAdd(&g_ctr, 1u);
        bar_sync(barid, 384);          // publish tile; A/prm free from prev epi
        unsigned tile = ctl[0];
        if (tile >= 1024u) break;
        int b = tile >> 8;
        int h = (tile >> 1) & 127;
        int pxg0 = (tile & 1) << 6;
        const float* xb = xt + (size_t)b * HWSZ * NC;

        float acc[2][4][4];
#pragma unroll
        for (int i = 0; i < 2; i++)
#pragma unroll
            for (int j = 0; j < 4; j++)
#pragma unroll
                for (int q = 0; q < 4; q++) acc[i][j][q] = 0.f;

        auto prmc = [&](int tap, int s) {
            if (tl < 64) {
                int px = tl;
                int pxg = pxg0 + px;
                int kh = tap / 3, kw = tap - 3 * kh;
                float offh = __ldg(&g_offsets[((b * NOFF + tap) * NH + h) * NW + pxg]);
                float offw_ = __ldg(&g_offsets[((b * NOFF + 9 + tap) * NH + h) * NW + pxg]);
                float ph = (float)kh + offh + (float)h + 1.f;
                float pw = (float)kw + offw_ + (float)pxg + 1.f;
                ph = fminf(fmaxf(ph, 0.f), 129.f);
                pw = fminf(fmaxf(pw, 0.f), 129.f);
                int h0 = (int)floorf(ph), w0 = (int)floorf(pw);
                int h1 = min(h0 + 1, 129), w1 = min(w0 + 1, 129);
                float wh1 = ph - (float)h0, wh0 = (float)h1 - ph;
                float ww1 = pw - (float)w0, ww0 = (float)w1 - pw;
                int ha = h0 - 1, hb2 = h1 - 1, wa = w0 - 1, wb2 = w1 - 1;
                float fh0 = ((unsigned)ha < 128u) ? wh0 : 0.f;
                float fh1 = ((unsigned)hb2 < 128u) ? wh1 : 0.f;
                float fw0 = ((unsigned)wa < 128u) ? ww0 : 0.f;
                float fw1 = ((unsigned)wb2 < 128u) ? ww1 : 0.f;
                int cha = min(max(ha, 0), 127), chb = min(max(hb2, 0), 127);
                int cwa = min(max(wa, 0), 127), cwb = min(max(wb2, 0), 127);
                prmF[s * 64 + px] = make_float4(fh0 * fw0, fh0 * fw1,
                                                fh1 * fw0, fh1 * fw1);
                ushort4 ii;
                ii.x = (unsigned short)(cha * NW + cwa);
                ii.y = (unsigned short)(cha * NW + cwb);
                ii.z = (unsigned short)(chb * NW + cwa);
                ii.w = (unsigned short)(chb * NW + cwb);
                prmI[s * 64 + px] = ii;
            }
        };

        auto gather = [&](int s) {
            char* aslot = aregion + s * 18432;
            for (int px = wl; px < 64; px += 12) {
                float4 f = prmF[s * 64 + px];
                ushort4 ii = prmI[s * 64 + px];
                unsigned long long c00 = ((const unsigned long long*)(xb + (size_t)ii.x * NC))[l];
                unsigned long long c01 = ((const unsigned long long*)(xb + (size_t)ii.y * NC))[l];
                unsigned long long c10 = ((const unsigned long long*)(xb + (size_t)ii.z * NC))[l];
                unsigned long long c11 = ((const unsigned long long*)(xb + (size_t)ii.w * NC))[l];
                unsigned long long v = 0ull;
                fma2(v, c00, dup2(f.x));
                fma2(v, c01, dup2(f.y));
                fma2(v, c10, dup2(f.z));
                fma2(v, c11, dup2(f.w));
                float v0, v1; unpack2(v, v0, v1);
                uint32_t hb = cvtbf2(v0, v1);
                float hf0 = __uint_as_float(hb << 16);
                float hf1 = __uint_as_float(hb & 0xFFFF0000u);
                uint32_t lb = cvtbf2(v0 - hf0, v1 - hf1);
                uint32_t off = (uint32_t)(px * 144 + l * 4);
                *(uint32_t*)(aslot + off) = hb;
                *(uint32_t*)(aslot + 9216 + off) = lb;
            }
        };

        prmc(0, 0);
        bar_sync(barid, 384);
        prmc(1, 1);
        gather(0);
        bar_sync(barid, 384);

        int tap3 = 0;
#pragma unroll 1
        for (int tap = 0; tap < 9; tap++) {
            int s = tap & 1;
            if (tap < 8) gather((tap + 1) & 1);

            if (tap3 == grp) {
                uint32_t abase = sb + SM_A + (uint32_t)(p * 36864 + s * 18432);
#pragma unroll
                for (int ks = 0; ks < 4; ks++) {
                    uint32_t a0 = abase + (a_lane + ks * 16 + (uint32_t)m0 * 72) * 2;
                    uint32_t b0 = sb + (b_lane + (uint32_t)(tap * 64 + ks * 16)) * 2;
                    uint32_t ah0[4], ah1[4], bh0[4], bh1[4];
                    ldsm4(ah0, a0);
                    ldsm4(ah1, a0 + 2304);       // +16 px rows * 144 B
                    ldsm4(bh0, b0);
                    ldsm4(bh1, b0 + 18688);      // +16 o rows * 1168 B
                    mma16816(acc[0][0], ah0, bh0[0], bh0[1]);
                    mma16816(acc[0][1], ah0, bh0[2], bh0[3]);
                    mma16816(acc[0][2], ah0, bh1[0], bh1[1]);
                    mma16816(acc[0][3], ah0, bh1[2], bh1[3]);
                    mma16816(acc[1][0], ah1, bh0[0], bh0[1]);
                    mma16816(acc[1][1], ah1, bh0[2], bh0[3]);
                    mma16816(acc[1][2], ah1, bh1[0], bh1[1]);
                    mma16816(acc[1][3], ah1, bh1[2], bh1[3]);
                    uint32_t al0[4], al1[4];
                    ldsm4(al0, a0 + 9216);
                    ldsm4(al1, a0 + 9216 + 2304);
                    mma16816(acc[0][0], al0, bh0[0], bh0[1]);
                    mma16816(acc[0][1], al0, bh0[2], bh0[3]);
                    mma16816(acc[0][2], al0, bh1[0], bh1[1]);
                    mma16816(acc[0][3], al0, bh1[2], bh1[3]);
                    mma16816(acc[1][0], al1, bh0[0], bh0[1]);
                    mma16816(acc[1][1], al1, bh0[2], bh0[3]);
                    mma16816(acc[1][2], al1, bh1[0], bh1[1]);
                    mma16816(acc[1][3], al1, bh1[2], bh1[3]);
                    uint32_t bl0[4], bl1[4];
                    ldsm4(bl0, b0 + 74752);
                    ldsm4(bl1, b0 + 74752 + 18688);
                    mma16816(acc[0][0], ah0, bl0[0], bl0[1]);
                    mma16816(acc[0][1], ah0, bl0[2], bl0[3]);
                    mma16816(acc[0][2], ah0, bl1[0], bl1[1]);
                    mma16816(acc[0][3], ah0, bl1[2], bl1[3]);
                    mma16816(acc[1][0], ah1, bl0[0], bl0[1]);
                    mma16816(acc[1][1], ah1, bl0[2], bl0[3]);
                    mma16816(acc[1][2], ah1, bl1[0], bl1[1]);
                    mma16816(acc[1][3], ah1, bl1[2], bl1[3]);
                }
            }
            if (tap < 7) prmc(tap + 2, tap & 1);
            if (++tap3 == 3) tap3 = 0;
            bar_sync(barid, 384);
        }

        // ---- epilogue: 3 tap-group partials reduced in smem (A region) ----
        float* Cs0 = (float*)aregion;            // 64 o x 68 = 17408 B
        float* Cs1 = (float*)(aregion + 17408);
        int g = l >> 2, cpair = (l & 3) * 2;
        if (grp < 2) {
            float* Cs = grp ? Cs1 : Cs0;
#pragma unroll
            for (int mt = 0; mt < 2; mt++)
#pragma unroll
                for (int nt = 0; nt < 4; nt++) {
                    int o = nq + nt * 8 + cpair;
                    int px = m0 + mt * 16;
                    Cs[o * 68 + px + g] = acc[mt][nt][0];
                    Cs[(o + 1) * 68 + px + g] = acc[mt][nt][1];
                    Cs[o * 68 + px + 8 + g] = acc[mt][nt][2];
                    Cs[(o + 1) * 68 + px + 8 + g] = acc[mt][nt][3];
                }
        }
        bar_sync(barid, 384);
        if (grp == 2) {
#pragma unroll
            for (int mt = 0; mt < 2; mt++)
#pragma unroll
                for (int nt = 0; nt < 4; nt++) {
                    int o = nq + nt * 8 + cpair;
                    int px = m0 + mt * 16;
                    Cs0[o * 68 + px + g] += acc[mt][nt][0];
                    Cs0[(o + 1) * 68 + px + g] += acc[mt][nt][1];
                    Cs0[o * 68 + px + 8 + g] += acc[mt][nt][2];
                    Cs0[(o + 1) * 68 + px + 8 + g] += acc[mt][nt][3];
                }
        }
        bar_sync(barid, 384);
        for (int o = wl; o < 64; o += 12) {
            float bs = __ldg(&bias[o]);
            float2 v = *(const float2*)&Cs0[o * 68 + l * 2];
            float2 u = *(const float2*)&Cs1[o * 68 + l * 2];
            v.x += u.x + bs; v.y += u.y + bs;
            *(float2*)(out + (((size_t)b * NO + o) * NH + h) * NW + pxg0 + l * 2) = v;
        }
    }
}

// ---------------------------------------------------------------------------
extern "C" void kernel_launch(void* const* d_in, const int* in_sizes, int n_in,
                              void* d_out, int out_size) {
    const float* x      = (const float*)d_in[0];
    const float* weight = (const float*)d_in[1];
    const float* bias   = (const float*)d_in[2];
    const float* offw   = (const float*)d_in[3];
    const float* offb   = (const float*)d_in[4];
    float* out = (float*)d_out;
    (void)in_sizes; (void)n_in; (void)out_size;

    cudaFuncSetAttribute(deform_kernel,
                         cudaFuncAttributeMaxDynamicSharedMemorySize, SMEM_SZ);

    wprep_kernel<<<(NO * NCK + 255) / 256, 256>>>(weight);
    nhwc_kernel<<<NB * NH, 256>>>(x);
    offsets_kernel<<<dim3(NH, NB), 128>>>(x, offw, offb);

    float* xt;
    cudaGetSymbolAddress((void**)&xt, g_xt);
    deform_kernel<<<152, 768, SMEM_SZ>>>(xt, bias, out);
}

// round 14
// speedup vs baseline: 1.0664x; 1.0664x over previous
#include <cuda_runtime.h>
#include <cuda_bf16.h>
#include <cstdint>

#define NB 4
#define NC 64
#define NH 128
#define NW 128
#define NO 64
#define NOFF 18
#define NCK 576
#define HWSZ (NH * NW)

__device__ float g_offsets[NB * NOFF * NH * NW];
__device__ float g_xt[NB * NH * NW * NC];        // NHWC
__device__ unsigned short g_wimg[74752];         // B hi[64][584] + lo[64][584]
__device__ unsigned int g_ctr;                   // dynamic tile counter

// ---- helpers -------------------------------------------------------------
__device__ __forceinline__ unsigned long long dup2(float v) {
    unsigned long long r; asm("mov.b64 %0, {%1, %1};" : "=l"(r) : "f"(v)); return r;
}
__device__ __forceinline__ unsigned long long pack2(float lo, float hi) {
    unsigned long long r; asm("mov.b64 %0, {%1, %2};" : "=l"(r) : "f"(lo), "f"(hi)); return r;
}
__device__ __forceinline__ void unpack2(unsigned long long v, float& lo, float& hi) {
    asm("mov.b64 {%0, %1}, %2;" : "=f"(lo), "=f"(hi) : "l"(v));
}
__device__ __forceinline__ void fma2(unsigned long long& d,
                                     unsigned long long a, unsigned long long b) {
    asm("fma.rn.f32x2 %0, %1, %2, %0;" : "+l"(d) : "l"(a), "l"(b));
}
__device__ __forceinline__ uint32_t smem_u32(const void* p) {
    uint32_t a;
    asm("{ .reg .u64 t; cvta.to.shared.u64 t, %1; cvt.u32.u64 %0, t; }" : "=r"(a) : "l"(p));
    return a;
}
__device__ __forceinline__ uint32_t cvtbf2(float alo, float ahi) {
    uint32_t r; asm("cvt.rn.bf16x2.f32 %0, %1, %2;" : "=r"(r) : "f"(ahi), "f"(alo)); return r;
}
__device__ __forceinline__ void ldsm4(uint32_t* r, uint32_t a) {
    asm volatile("ldmatrix.sync.aligned.m8n8.x4.shared.b16 {%0,%1,%2,%3}, [%4];"
        : "=r"(r[0]), "=r"(r[1]), "=r"(r[2]), "=r"(r[3]) : "r"(a));
}
__device__ __forceinline__ void mma16816(float* c, const uint32_t* a,
                                         uint32_t b0, uint32_t b1) {
    asm volatile("mma.sync.aligned.m16n8k16.row.col.f32.bf16.bf16.f32 "
        "{%0,%1,%2,%3}, {%4,%5,%6,%7}, {%8,%9}, {%0,%1,%2,%3};"
        : "+f"(c[0]), "+f"(c[1]), "+f"(c[2]), "+f"(c[3])
        : "r"(a[0]), "r"(a[1]), "r"(a[2]), "r"(a[3]), "r"(b0), "r"(b1));
}
__device__ __forceinline__ void bar_sync(int id, int cnt) {
    asm volatile("bar.sync %0, %1;" :: "r"(id), "r"(cnt) : "memory");
}

// ---------------------------------------------------------------------------
// Kernel 0: weight -> hi/lo bf16 B images; also resets the tile counter.
// ---------------------------------------------------------------------------
__global__ void wprep_kernel(const float* __restrict__ weight) {
    if (blockIdx.x == 0 && threadIdx.x == 0) g_ctr = 0u;
    int idx = blockIdx.x * 256 + threadIdx.x;
    if (idx < NO * NCK) {
        int o = idx / NCK;
        int r = idx - o * NCK;
        int c = r / 9;
        int k = r - c * 9;
        float v = weight[idx];
        __nv_bfloat16 hb = __float2bfloat16(v);
        __nv_bfloat16 lb = __float2bfloat16(v - __bfloat162float(hb));
        int i16 = o * 584 + k * 64 + c;
        g_wimg[i16] = *(unsigned short*)&hb;
        g_wimg[37376 + i16] = *(unsigned short*)&lb;
    }
}

// ---------------------------------------------------------------------------
// Kernel 1: merged prep. Block = one (b,h) row, 256 threads.
// Warps 0-3: offsets conv (f32x2). Warps 4-7: NCHW->NHWC transpose.
// ---------------------------------------------------------------------------
__global__ __launch_bounds__(256) void prep_kernel(
    const float* __restrict__ x, const float* __restrict__ offw,
    const float* __restrict__ offb)
{
    __shared__ __align__(16) float ws2[9 * NC * 10 * 2];  // 46080 B
    __shared__ float ts[NC * 129];                        // 33024 B
    int t = threadIdx.x;
    int h = blockIdx.x, b = blockIdx.y;

    if (t < 128) {
        // ===== offsets conv (threads 0-127, barrier 1) =====
        for (int i = t; i < 9 * NC * 10 * 2; i += 128) ws2[i] = 0.f;
        bar_sync(1, 128);
        for (int i = t; i < NOFF * NC * 9; i += 128) {
            int kk = i / (NC * 9);
            int rem = i - kk * (NC * 9);
            int c = rem / 9;
            int tap = rem - c * 9;
            ws2[((tap * NC + c) * 10 + (kk >> 1)) * 2 + (kk & 1)] = offw[i];
        }
        int w = t;
        unsigned long long acc[9];
#pragma unroll
        for (int j = 0; j < 9; j++)
            acc[j] = pack2(__ldg(&offb[2 * j]), __ldg(&offb[2 * j + 1]));
        bar_sync(1, 128);
        bool ok9[9]; int idx9[9];
#pragma unroll
        for (int dh = 0; dh < 3; dh++)
#pragma unroll
            for (int dw = 0; dw < 3; dw++) {
                int hh = h + dh - 1, ww2 = w + dw - 1;
                ok9[dh * 3 + dw] = (hh >= 0 && hh < NH && ww2 >= 0 && ww2 < NW);
                idx9[dh * 3 + dw] = hh * NW + ww2;
            }
        const float* xb = x + (size_t)b * NC * HWSZ;
        for (int c = 0; c < NC; c++) {
            const float* xc = xb + c * HWSZ;
            float v[9];
#pragma unroll
            for (int k = 0; k < 9; k++) v[k] = ok9[k] ? __ldg(&xc[idx9[k]]) : 0.f;
#pragma unroll
            for (int tap = 0; tap < 9; tap++) {
                unsigned long long vd = dup2(v[tap]);
                const ulonglong2* wq = (const ulonglong2*)&ws2[(tap * NC + c) * 20];
                ulonglong2 q0 = wq[0], q1 = wq[1], q2 = wq[2], q3 = wq[3], q4 = wq[4];
                fma2(acc[0], vd, q0.x); fma2(acc[1], vd, q0.y);
                fma2(acc[2], vd, q1.x); fma2(acc[3], vd, q1.y);
                fma2(acc[4], vd, q2.x); fma2(acc[5], vd, q2.y);
                fma2(acc[6], vd, q3.x); fma2(acc[7], vd, q3.y);
                fma2(acc[8], vd, q4.x);
            }
        }
#pragma unroll
        for (int j = 0; j < 9; j++) {
            float lo, hi; unpack2(acc[j], lo, hi);
            g_offsets[((b * NOFF + 2 * j) * NH + h) * NW + w] = lo;
            g_offsets[((b * NOFF + 2 * j + 1) * NH + h) * NW + w] = hi;
        }
    } else {
        // ===== NHWC transpose (threads 128-255, barrier 2) =====
        int t2 = t - 128;
        for (int i = t2; i < NC * NW; i += 128) {
            int c = i >> 7, w2 = i & 127;
            ts[c * 129 + w2] = x[((size_t)(b * NC + c) * NH + h) * NW + w2];
        }
        bar_sync(2, 128);
        for (int i = t2; i < NC * NW; i += 128) {
            int w2 = i >> 6, c = i & 63;
            g_xt[(((size_t)(b * NH + h) * NW) + w2) * NC + c] = ts[c * 129 + w2];
        }
    }
}

// ---------------------------------------------------------------------------
// Kernel 2: HMMA deform (R12 structure: 2 pipelines x 16 warps, 16x16 warp
// tiles) + dynamic tile stealing. 64-px half-row tiles (1024 total).
// SMEM: B 149504 | A 2x2x18432 | prm 2x3072 | ctl 128 = 229504 B.
// ---------------------------------------------------------------------------
#define SM_A 149504
#define SM_PRM 223232
#define SM_CTL 229376
#define SMEM_SZ 229504

__global__ __launch_bounds__(1024, 1) void deform_kernel(
    const float* __restrict__ xt, const float* __restrict__ bias,
    float* __restrict__ out)
{
    extern __shared__ __align__(16) char sm[];
    uint32_t sb = smem_u32(sm);
    int t = threadIdx.x, l = t & 31, wi = t >> 5;
    int p = wi >> 4;               // pipeline 0/1
    int wl = wi & 15;              // warp in pipeline
    int tl = t & 511;              // thread in pipeline
    int barid = 1 + p;
    int m0 = (wl >> 2) * 16;       // local m-tile (0..48)
    int nq = (wl & 3) * 16;        // n-quarter

    {   // load B images once (all threads)
        const float4* src = (const float4*)g_wimg;
        float4* dst = (float4*)sm;
        for (int i = t; i < 9344; i += 1024) dst[i] = src[i];
    }
    __syncthreads();

    uint32_t a_lane = (uint32_t)((l & 15) * 72 + ((l >> 4) << 3));
    uint32_t b_lane = (uint32_t)((nq + (l & 7) + ((l >> 4) << 3)) * 584 + (l & 8));

    char* aregion = sm + SM_A + p * 36864;                     // 2 slots x 18432
    float4* prmF = (float4*)(sm + SM_PRM + p * 3072);          // [2][64]
    ushort4* prmI = (ushort4*)(sm + SM_PRM + p * 3072 + 2048); // [2][64]
    unsigned* ctl = (unsigned*)(sm + SM_CTL) + p * 16;

    for (;;) {
        if (tl == 0) ctl[0] = atomicAdd(&g_ctr, 1u);
        bar_sync(barid, 512);      // publish tile; A/prm free from prev epilogue
        unsigned tile = ctl[0];
        if (tile >= 1024u) break;
        int b = tile >> 8;
        int h = (tile >> 1) & 127;
        int pxg0 = (tile & 1) << 6;
        const float* xb = xt + (size_t)b * HWSZ * NC;

        float acc[2][4];
#pragma unroll
        for (int i = 0; i < 2; i++)
#pragma unroll
            for (int j = 0; j < 4; j++) acc[i][j] = 0.f;

        auto prmc = [&](int tap, int s) {
            if (tl < 64) {
                int px = tl;
                int pxg = pxg0 + px;
                int kh = tap / 3, kw = tap - 3 * kh;
                float offh = __ldg(&g_offsets[((b * NOFF + tap) * NH + h) * NW + pxg]);
                float offw_ = __ldg(&g_offsets[((b * NOFF + 9 + tap) * NH + h) * NW + pxg]);
                float ph = (float)kh + offh + (float)h + 1.f;
                float pw = (float)kw + offw_ + (float)pxg + 1.f;
                ph = fminf(fmaxf(ph, 0.f), 129.f);
                pw = fminf(fmaxf(pw, 0.f), 129.f);
                int h0 = (int)floorf(ph), w0 = (int)floorf(pw);
                int h1 = min(h0 + 1, 129), w1 = min(w0 + 1, 129);
                float wh1 = ph - (float)h0, wh0 = (float)h1 - ph;
                float ww1 = pw - (float)w0, ww0 = (float)w1 - pw;
                int ha = h0 - 1, hb2 = h1 - 1, wa = w0 - 1, wb2 = w1 - 1;
                float fh0 = ((unsigned)ha < 128u) ? wh0 : 0.f;
                float fh1 = ((unsigned)hb2 < 128u) ? wh1 : 0.f;
                float fw0 = ((unsigned)wa < 128u) ? ww0 : 0.f;
                float fw1 = ((unsigned)wb2 < 128u) ? ww1 : 0.f;
                int cha = min(max(ha, 0), 127), chb = min(max(hb2, 0), 127);
                int cwa = min(max(wa, 0), 127), cwb = min(max(wb2, 0), 127);
                prmF[s * 64 + px] = make_float4(fh0 * fw0, fh0 * fw1,
                                                fh1 * fw0, fh1 * fw1);
                ushort4 ii;
                ii.x = (unsigned short)(cha * NW + cwa);
                ii.y = (unsigned short)(cha * NW + cwb);
                ii.z = (unsigned short)(chb * NW + cwa);
                ii.w = (unsigned short)(chb * NW + cwb);
                prmI[s * 64 + px] = ii;
            }
        };

        auto gather = [&](int s) {
            char* aslot = aregion + s * 18432;
#pragma unroll
            for (int it = 0; it < 4; it++) {
                int px = it * 16 + wl;
                float4 f = prmF[s * 64 + px];
                ushort4 ii = prmI[s * 64 + px];
                unsigned long long c00 = ((const unsigned long long*)(xb + (size_t)ii.x * NC))[l];
                unsigned long long c01 = ((const unsigned long long*)(xb + (size_t)ii.y * NC))[l];
                unsigned long long c10 = ((const unsigned long long*)(xb + (size_t)ii.z * NC))[l];
                unsigned long long c11 = ((const unsigned long long*)(xb + (size_t)ii.w * NC))[l];
                unsigned long long v = 0ull;
                fma2(v, c00, dup2(f.x));
                fma2(v, c01, dup2(f.y));
                fma2(v, c10, dup2(f.z));
                fma2(v, c11, dup2(f.w));
                float v0, v1; unpack2(v, v0, v1);
                uint32_t hb = cvtbf2(v0, v1);
                float hf0 = __uint_as_float(hb << 16);
                float hf1 = __uint_as_float(hb & 0xFFFF0000u);
                uint32_t lb = cvtbf2(v0 - hf0, v1 - hf1);
                uint32_t off = (uint32_t)(px * 144 + l * 4);
                *(uint32_t*)(aslot + off) = hb;
                *(uint32_t*)(aslot + 9216 + off) = lb;
            }
        };

        prmc(0, 0);
        bar_sync(barid, 512);
        prmc(1, 1);
        gather(0);
        bar_sync(barid, 512);

#pragma unroll 1
        for (int tap = 0; tap < 9; tap++) {
            int s = tap & 1;
            if (tap < 8) gather((tap + 1) & 1);

            uint32_t abase = sb + SM_A + (uint32_t)(p * 36864 + s * 18432);
#pragma unroll
            for (int ks = 0; ks < 4; ks++) {
                uint32_t ah[4], al[4], bh[4], bl[4];
                uint32_t aoff = abase + (a_lane + ks * 16 + (uint32_t)m0 * 72) * 2;
                ldsm4(ah, aoff);
                ldsm4(al, aoff + 9216);
                uint32_t boff = sb + (b_lane + (uint32_t)(tap * 64 + ks * 16)) * 2;
                ldsm4(bh, boff);
                ldsm4(bl, boff + 74752);
#pragma unroll
                for (int nt = 0; nt < 2; nt++) {
                    mma16816(acc[nt], ah, bh[nt * 2], bh[nt * 2 + 1]);
                    mma16816(acc[nt], ah, bl[nt * 2], bl[nt * 2 + 1]);
                    mma16816(acc[nt], al, bh[nt * 2], bh[nt * 2 + 1]);
                }
            }
            if (tap < 7) prmc(tap + 2, tap & 1);
            bar_sync(barid, 512);
        }

        // ---- epilogue: stage to Cs[o][px64] (reuse A region), coalesced out ----
        float* Cs = (float*)aregion;   // 64 o x 68 stride = 17408 B
        int g = l >> 2, cpair = (l & 3) * 2;
#pragma unroll
        for (int nt = 0; nt < 2; nt++) {
            int o = nq + nt * 8 + cpair;
            Cs[o * 68 + m0 + g] = acc[nt][0];
            Cs[(o + 1) * 68 + m0 + g] = acc[nt][1];
            Cs[o * 68 + m0 + 8 + g] = acc[nt][2];
            Cs[(o + 1) * 68 + m0 + 8 + g] = acc[nt][3];
        }
        bar_sync(barid, 512);
#pragma unroll
        for (int oo = 0; oo < 4; oo++) {
            int o = wl * 4 + oo;
            float bs = __ldg(&bias[o]);
            float2 v = *(const float2*)&Cs[o * 68 + l * 2];
            v.x += bs; v.y += bs;
            *(float2*)(out + (((size_t)b * NO + o) * NH + h) * NW + pxg0 + l * 2) = v;
        }
    }
}

// ---------------------------------------------------------------------------
extern "C" void kernel_launch(void* const* d_in, const int* in_sizes, int n_in,
                              void* d_out, int out_size) {
    const float* x      = (const float*)d_in[0];
    const float* weight = (const float*)d_in[1];
    const float* bias   = (const float*)d_in[2];
    const float* offw   = (const float*)d_in[3];
    const float* offb   = (const float*)d_in[4];
    float* out = (float*)d_out;
    (void)in_sizes; (void)n_in; (void)out_size;

    cudaFuncSetAttribute(deform_kernel,
                         cudaFuncAttributeMaxDynamicSharedMemorySize, SMEM_SZ);

    wprep_kernel<<<(NO * NCK + 255) / 256, 256>>>(weight);
    prep_kernel<<<dim3(NH, NB), 256>>>(x, offw, offb);

    float* xt;
    cudaGetSymbolAddress((void**)&xt, g_xt);
    deform_kernel<<<152, 1024, SMEM_SZ>>>(xt, bias, out);
}

// round 15
// speedup vs baseline: 1.1330x; 1.0625x over previous
#include <cuda_runtime.h>
#include <cuda_bf16.h>
#include <cstdint>

#define NB 4
#define NC 64
#define NH 128
#define NW 128
#define NO 64
#define NOFF 18
#define NCK 576
#define HWSZ (NH * NW)

__device__ float g_offsets[NB * NOFF * NH * NW];
__device__ float g_xt[NB * NH * NW * NC];        // NHWC
__device__ unsigned short g_wimg[74752];         // B hi[64][584] + lo[64][584]
__device__ unsigned int g_ctr;                   // dynamic tile counter

// ---- helpers -------------------------------------------------------------
__device__ __forceinline__ unsigned long long dup2(float v) {
    unsigned long long r; asm("mov.b64 %0, {%1, %1};" : "=l"(r) : "f"(v)); return r;
}
__device__ __forceinline__ unsigned long long pack2(float lo, float hi) {
    unsigned long long r; asm("mov.b64 %0, {%1, %2};" : "=l"(r) : "f"(lo), "f"(hi)); return r;
}
__device__ __forceinline__ void unpack2(unsigned long long v, float& lo, float& hi) {
    asm("mov.b64 {%0, %1}, %2;" : "=f"(lo), "=f"(hi) : "l"(v));
}
__device__ __forceinline__ void fma2(unsigned long long& d,
                                     unsigned long long a, unsigned long long b) {
    asm("fma.rn.f32x2 %0, %1, %2, %0;" : "+l"(d) : "l"(a), "l"(b));
}
__device__ __forceinline__ uint32_t smem_u32(const void* p) {
    uint32_t a;
    asm("{ .reg .u64 t; cvta.to.shared.u64 t, %1; cvt.u32.u64 %0, t; }" : "=r"(a) : "l"(p));
    return a;
}
__device__ __forceinline__ uint32_t cvtbf2(float alo, float ahi) {
    uint32_t r; asm("cvt.rn.bf16x2.f32 %0, %1, %2;" : "=r"(r) : "f"(ahi), "f"(alo)); return r;
}
__device__ __forceinline__ void ldsm4(uint32_t* r, uint32_t a) {
    asm volatile("ldmatrix.sync.aligned.m8n8.x4.shared.b16 {%0,%1,%2,%3}, [%4];"
        : "=r"(r[0]), "=r"(r[1]), "=r"(r[2]), "=r"(r[3]) : "r"(a));
}
__device__ __forceinline__ void mma16816(float* c, const uint32_t* a,
                                         uint32_t b0, uint32_t b1) {
    asm volatile("mma.sync.aligned.m16n8k16.row.col.f32.bf16.bf16.f32 "
        "{%0,%1,%2,%3}, {%4,%5,%6,%7}, {%8,%9}, {%0,%1,%2,%3};"
        : "+f"(c[0]), "+f"(c[1]), "+f"(c[2]), "+f"(c[3])
        : "r"(a[0]), "r"(a[1]), "r"(a[2]), "r"(a[3]), "r"(b0), "r"(b1));
}
__device__ __forceinline__ void bar_sync(int id, int cnt) {
    asm volatile("bar.sync %0, %1;" :: "r"(id), "r"(cnt) : "memory");
}

// ---------------------------------------------------------------------------
// Kernel 0: weight -> hi/lo bf16 B images; also resets the tile counter.
// ---------------------------------------------------------------------------
__global__ void wprep_kernel(const float* __restrict__ weight) {
    if (blockIdx.x == 0 && threadIdx.x == 0) g_ctr = 0u;
    int idx = blockIdx.x * 256 + threadIdx.x;
    if (idx < NO * NCK) {
        int o = idx / NCK;
        int r = idx - o * NCK;
        int c = r / 9;
        int k = r - c * 9;
        float v = weight[idx];
        __nv_bfloat16 hb = __float2bfloat16(v);
        __nv_bfloat16 lb = __float2bfloat16(v - __bfloat162float(hb));
        int i16 = o * 584 + k * 64 + c;
        g_wimg[i16] = *(unsigned short*)&hb;
        g_wimg[37376 + i16] = *(unsigned short*)&lb;
    }
}

// ---------------------------------------------------------------------------
// Kernel 1: merged prep. Block = one (b,h) row, 256 threads.
// Warps 0-3: offsets conv (f32x2). Warps 4-7: NCHW->NHWC transpose.
// ---------------------------------------------------------------------------
__global__ __launch_bounds__(256) void prep_kernel(
    const float* __restrict__ x, const float* __restrict__ offw,
    const float* __restrict__ offb)
{
    __shared__ __align__(16) float ws2[9 * NC * 10 * 2];  // 46080 B
    __shared__ float ts[NC * 129];                        // 33024 B
    int t = threadIdx.x;
    int h = blockIdx.x, b = blockIdx.y;

    if (t < 128) {
        for (int i = t; i < 9 * NC * 10 * 2; i += 128) ws2[i] = 0.f;
        bar_sync(1, 128);
        for (int i = t; i < NOFF * NC * 9; i += 128) {
            int kk = i / (NC * 9);
            int rem = i - kk * (NC * 9);
            int c = rem / 9;
            int tap = rem - c * 9;
            ws2[((tap * NC + c) * 10 + (kk >> 1)) * 2 + (kk & 1)] = offw[i];
        }
        int w = t;
        unsigned long long acc[9];
#pragma unroll
        for (int j = 0; j < 9; j++)
            acc[j] = pack2(__ldg(&offb[2 * j]), __ldg(&offb[2 * j + 1]));
        bar_sync(1, 128);
        bool ok9[9]; int idx9[9];
#pragma unroll
        for (int dh = 0; dh < 3; dh++)
#pragma unroll
            for (int dw = 0; dw < 3; dw++) {
                int hh = h + dh - 1, ww2 = w + dw - 1;
                ok9[dh * 3 + dw] = (hh >= 0 && hh < NH && ww2 >= 0 && ww2 < NW);
                idx9[dh * 3 + dw] = hh * NW + ww2;
            }
        const float* xb = x + (size_t)b * NC * HWSZ;
        for (int c = 0; c < NC; c++) {
            const float* xc = xb + c * HWSZ;
            float v[9];
#pragma unroll
            for (int k = 0; k < 9; k++) v[k] = ok9[k] ? __ldg(&xc[idx9[k]]) : 0.f;
#pragma unroll
            for (int tap = 0; tap < 9; tap++) {
                unsigned long long vd = dup2(v[tap]);
                const ulonglong2* wq = (const ulonglong2*)&ws2[(tap * NC + c) * 20];
                ulonglong2 q0 = wq[0], q1 = wq[1], q2 = wq[2], q3 = wq[3], q4 = wq[4];
                fma2(acc[0], vd, q0.x); fma2(acc[1], vd, q0.y);
                fma2(acc[2], vd, q1.x); fma2(acc[3], vd, q1.y);
                fma2(acc[4], vd, q2.x); fma2(acc[5], vd, q2.y);
                fma2(acc[6], vd, q3.x); fma2(acc[7], vd, q3.y);
                fma2(acc[8], vd, q4.x);
            }
        }
#pragma unroll
        for (int j = 0; j < 9; j++) {
            float lo, hi; unpack2(acc[j], lo, hi);
            g_offsets[((b * NOFF + 2 * j) * NH + h) * NW + w] = lo;
            g_offsets[((b * NOFF + 2 * j + 1) * NH + h) * NW + w] = hi;
        }
    } else {
        int t2 = t - 128;
        for (int i = t2; i < NC * NW; i += 128) {
            int c = i >> 7, w2 = i & 127;
            ts[c * 129 + w2] = x[((size_t)(b * NC + c) * NH + h) * NW + w2];
        }
        bar_sync(2, 128);
        for (int i = t2; i < NC * NW; i += 128) {
            int w2 = i >> 6, c = i & 63;
            g_xt[(((size_t)(b * NH + h) * NW) + w2) * NC + c] = ts[c * 129 + w2];
        }
    }
}

// ---------------------------------------------------------------------------
// Kernel 2: HMMA deform. FOUR independent 256-thread pipelines per block.
// 1024 thr; pipeline p = warps p*8..p*8+7; tile = 32-px quarter-row
// (2048 tiles, dynamic stealing). Warp: m-tile=(wl>>2)*16, n-quarter=(wl&3)*16.
// SMEM: B 149504 | A 4 pipes x 2 slots x 9216 | prm 4x1536 | ctl 128 = 229504.
// ---------------------------------------------------------------------------
#define SM_A 149504
#define SM_PRM 223232
#define SM_CTL 229376
#define SMEM_SZ 229504

__global__ __launch_bounds__(1024, 1) void deform_kernel(
    const float* __restrict__ xt, const float* __restrict__ bias,
    float* __restrict__ out)
{
    extern __shared__ __align__(16) char sm[];
    uint32_t sb = smem_u32(sm);
    int t = threadIdx.x, l = t & 31, wi = t >> 5;
    int p = wi >> 3;               // pipeline 0..3
    int wl = wi & 7;               // warp in pipeline
    int tl = t & 255;              // thread in pipeline
    int barid = 1 + p;
    int m0 = (wl >> 2) * 16;       // 0 or 16 (local px)
    int nq = (wl & 3) * 16;        // 0,16,32,48

    {   // load B images once (all threads)
        const float4* src = (const float4*)g_wimg;
        float4* dst = (float4*)sm;
        for (int i = t; i < 9344; i += 1024) dst[i] = src[i];
    }
    __syncthreads();

    uint32_t a_lane = (uint32_t)((l & 15) * 72 + ((l >> 4) << 3));
    uint32_t b_lane = (uint32_t)((nq + (l & 7) + ((l >> 4) << 3)) * 584 + (l & 8));

    char* aregion = sm + SM_A + p * 18432;                     // 2 slots x 9216
    float4* prmF = (float4*)(sm + SM_PRM + p * 1536);          // [2][32]
    ushort4* prmI = (ushort4*)(sm + SM_PRM + p * 1536 + 1024); // [2][32]
    unsigned* ctl = (unsigned*)(sm + SM_CTL) + p * 8;

    for (;;) {
        if (tl == 0) ctl[0] = atomicAdd(&g_ctr, 1u);
        bar_sync(barid, 256);      // publish tile; A/prm free from prev epilogue
        unsigned tile = ctl[0];
        if (tile >= 2048u) break;
        int b = tile >> 9;
        int h = (tile >> 2) & 127;
        int pxg0 = (tile & 3) << 5;
        const float* xb = xt + (size_t)b * HWSZ * NC;

        float acc[2][4];
#pragma unroll
        for (int i = 0; i < 2; i++)
#pragma unroll
            for (int j = 0; j < 4; j++) acc[i][j] = 0.f;

        auto prmc = [&](int tap, int s) {
            if (tl < 32) {
                int px = tl;
                int pxg = pxg0 + px;
                int kh = tap / 3, kw = tap - 3 * kh;
                float offh = __ldg(&g_offsets[((b * NOFF + tap) * NH + h) * NW + pxg]);
                float offw_ = __ldg(&g_offsets[((b * NOFF + 9 + tap) * NH + h) * NW + pxg]);
                float ph = (float)kh + offh + (float)h + 1.f;
                float pw = (float)kw + offw_ + (float)pxg + 1.f;
                ph = fminf(fmaxf(ph, 0.f), 129.f);
                pw = fminf(fmaxf(pw, 0.f), 129.f);
                int h0 = (int)floorf(ph), w0 = (int)floorf(pw);
                int h1 = min(h0 + 1, 129), w1 = min(w0 + 1, 129);
                float wh1 = ph - (float)h0, wh0 = (float)h1 - ph;
                float ww1 = pw - (float)w0, ww0 = (float)w1 - pw;
                int ha = h0 - 1, hb2 = h1 - 1, wa = w0 - 1, wb2 = w1 - 1;
                float fh0 = ((unsigned)ha < 128u) ? wh0 : 0.f;
                float fh1 = ((unsigned)hb2 < 128u) ? wh1 : 0.f;
                float fw0 = ((unsigned)wa < 128u) ? ww0 : 0.f;
                float fw1 = ((unsigned)wb2 < 128u) ? ww1 : 0.f;
                int cha = min(max(ha, 0), 127), chb = min(max(hb2, 0), 127);
                int cwa = min(max(wa, 0), 127), cwb = min(max(wb2, 0), 127);
                prmF[s * 32 + px] = make_float4(fh0 * fw0, fh0 * fw1,
                                                fh1 * fw0, fh1 * fw1);
                ushort4 ii;
                ii.x = (unsigned short)(cha * NW + cwa);
                ii.y = (unsigned short)(cha * NW + cwb);
                ii.z = (unsigned short)(chb * NW + cwa);
                ii.w = (unsigned short)(chb * NW + cwb);
                prmI[s * 32 + px] = ii;
            }
        };

        auto gather = [&](int s) {
            char* aslot = aregion + s * 9216;
#pragma unroll
            for (int it = 0; it < 4; it++) {
                int px = it * 8 + wl;
                float4 f = prmF[s * 32 + px];
                ushort4 ii = prmI[s * 32 + px];
                unsigned long long c00 = ((const unsigned long long*)(xb + (size_t)ii.x * NC))[l];
                unsigned long long c01 = ((const unsigned long long*)(xb + (size_t)ii.y * NC))[l];
                unsigned long long c10 = ((const unsigned long long*)(xb + (size_t)ii.z * NC))[l];
                unsigned long long c11 = ((const unsigned long long*)(xb + (size_t)ii.w * NC))[l];
                unsigned long long v = 0ull;
                fma2(v, c00, dup2(f.x));
                fma2(v, c01, dup2(f.y));
                fma2(v, c10, dup2(f.z));
                fma2(v, c11, dup2(f.w));
                float v0, v1; unpack2(v, v0, v1);
                uint32_t hb = cvtbf2(v0, v1);
                float hf0 = __uint_as_float(hb << 16);
                float hf1 = __uint_as_float(hb & 0xFFFF0000u);
                uint32_t lb = cvtbf2(v0 - hf0, v1 - hf1);
                uint32_t off = (uint32_t)(px * 144 + l * 4);
                *(uint32_t*)(aslot + off) = hb;
                *(uint32_t*)(aslot + 4608 + off) = lb;
            }
        };

        prmc(0, 0);
        bar_sync(barid, 256);
        prmc(1, 1);
        gather(0);
        bar_sync(barid, 256);

#pragma unroll 1
        for (int tap = 0; tap < 9; tap++) {
            int s = tap & 1;
            if (tap < 8) gather((tap + 1) & 1);

            uint32_t abase = sb + SM_A + (uint32_t)(p * 18432 + s * 9216);
#pragma unroll
            for (int ks = 0; ks < 4; ks++) {
                uint32_t ah[4], al[4], bh[4], bl[4];
                uint32_t aoff = abase + (a_lane + ks * 16 + (uint32_t)m0 * 72) * 2;
                ldsm4(ah, aoff);
                ldsm4(al, aoff + 4608);
                uint32_t boff = sb + (b_lane + (uint32_t)(tap * 64 + ks * 16)) * 2;
                ldsm4(bh, boff);
                ldsm4(bl, boff + 74752);
#pragma unroll
                for (int nt = 0; nt < 2; nt++) {
                    mma16816(acc[nt], ah, bh[nt * 2], bh[nt * 2 + 1]);
                    mma16816(acc[nt], ah, bl[nt * 2], bl[nt * 2 + 1]);
                    mma16816(acc[nt], al, bh[nt * 2], bh[nt * 2 + 1]);
                }
            }
            if (tap < 7) prmc(tap + 2, tap & 1);
            bar_sync(barid, 256);
        }

        // ---- epilogue: stage to Cs[o][px32] (reuse A region), coalesced out ----
        float* Cs = (float*)aregion;   // 64 o x 36 stride = 9216 B
        int g = l >> 2, cpair = (l & 3) * 2;
#pragma unroll
        for (int nt = 0; nt < 2; nt++) {
            int o = nq + nt * 8 + cpair;
            Cs[o * 36 + m0 + g] = acc[nt][0];
            Cs[(o + 1) * 36 + m0 + g] = acc[nt][1];
            Cs[o * 36 + m0 + 8 + g] = acc[nt][2];
            Cs[(o + 1) * 36 + m0 + 8 + g] = acc[nt][3];
        }
        bar_sync(barid, 256);
#pragma unroll
        for (int oo = 0; oo < 8; oo++) {
            int o = wl * 8 + oo;
            float bs = __ldg(&bias[o]);
            float v = Cs[o * 36 + l] + bs;
            out[(((size_t)b * NO + o) * NH + h) * NW + pxg0 + l] = v;
        }
    }
}

// ---------------------------------------------------------------------------
extern "C" void kernel_launch(void* const* d_in, const int* in_sizes, int n_in,
                              void* d_out, int out_size) {
    const float* x      = (const float*)d_in[0];
    const float* weight = (const float*)d_in[1];
    const float* bias   = (const float*)d_in[2];
    const float* offw   = (const float*)d_in[3];
    const float* offb   = (const float*)d_in[4];
    float* out = (float*)d_out;
    (void)in_sizes; (void)n_in; (void)out_size;

    cudaFuncSetAttribute(deform_kernel,
                         cudaFuncAttributeMaxDynamicSharedMemorySize, SMEM_SZ);

    wprep_kernel<<<(NO * NCK + 255) / 256, 256>>>(weight);
    prep_kernel<<<dim3(NH, NB), 256>>>(x, offw, offb);

    float* xt;
    cudaGetSymbolAddress((void**)&xt, g_xt);
    deform_kernel<<<152, 1024, SMEM_SZ>>>(xt, bias, out);
}

// round 16
// speedup vs baseline: 1.1667x; 1.0298x over previous
#include <cuda_runtime.h>
#include <cuda_bf16.h>
#include <cstdint>

#define NB 4
#define NC 64
#define NH 128
#define NW 128
#define NO 64
#define NOFF 18
#define NCK 576
#define HWSZ (NH * NW)

__device__ float g_offsets[NB * NOFF * NH * NW];
__device__ float g_xt[NB * NH * NW * NC];        // NHWC
__device__ unsigned short g_wimg[74752];         // B hi[64][584] + lo[64][584]
__device__ unsigned int g_ctr;                   // dynamic tile counter

// ---- helpers -------------------------------------------------------------
__device__ __forceinline__ unsigned long long dup2(float v) {
    unsigned long long r; asm("mov.b64 %0, {%1, %1};" : "=l"(r) : "f"(v)); return r;
}
__device__ __forceinline__ unsigned long long pack2(float lo, float hi) {
    unsigned long long r; asm("mov.b64 %0, {%1, %2};" : "=l"(r) : "f"(lo), "f"(hi)); return r;
}
__device__ __forceinline__ void unpack2(unsigned long long v, float& lo, float& hi) {
    asm("mov.b64 {%0, %1}, %2;" : "=f"(lo), "=f"(hi) : "l"(v));
}
__device__ __forceinline__ void fma2(unsigned long long& d,
                                     unsigned long long a, unsigned long long b) {
    asm("fma.rn.f32x2 %0, %1, %2, %0;" : "+l"(d) : "l"(a), "l"(b));
}
__device__ __forceinline__ uint32_t smem_u32(const void* p) {
    uint32_t a;
    asm("{ .reg .u64 t; cvta.to.shared.u64 t, %1; cvt.u32.u64 %0, t; }" : "=r"(a) : "l"(p));
    return a;
}
__device__ __forceinline__ uint32_t cvtbf2(float alo, float ahi) {
    uint32_t r; asm("cvt.rn.bf16x2.f32 %0, %1, %2;" : "=r"(r) : "f"(ahi), "f"(alo)); return r;
}
__device__ __forceinline__ void ldsm4(uint32_t* r, uint32_t a) {
    asm volatile("ldmatrix.sync.aligned.m8n8.x4.shared.b16 {%0,%1,%2,%3}, [%4];"
        : "=r"(r[0]), "=r"(r[1]), "=r"(r[2]), "=r"(r[3]) : "r"(a));
}
__device__ __forceinline__ void mma16816(float* c, const uint32_t* a,
                                         uint32_t b0, uint32_t b1) {
    asm volatile("mma.sync.aligned.m16n8k16.row.col.f32.bf16.bf16.f32 "
        "{%0,%1,%2,%3}, {%4,%5,%6,%7}, {%8,%9}, {%0,%1,%2,%3};"
        : "+f"(c[0]), "+f"(c[1]), "+f"(c[2]), "+f"(c[3])
        : "r"(a[0]), "r"(a[1]), "r"(a[2]), "r"(a[3]), "r"(b0), "r"(b1));
}
__device__ __forceinline__ void bar_sync(int id, int cnt) {
    asm volatile("bar.sync %0, %1;" :: "r"(id), "r"(cnt) : "memory");
}

// ---------------------------------------------------------------------------
// Kernel 1: merged prep. Block = one (b,h) row, 256 threads.
// Warps 0-3: offsets conv (f32x2). Warps 4-7: NCHW->NHWC transpose.
// All blocks: 72-element chunk of weight->bf16 hi/lo prep. Block 0: ctr reset.
// ---------------------------------------------------------------------------
__global__ __launch_bounds__(256) void prep_kernel(
    const float* __restrict__ x, const float* __restrict__ offw,
    const float* __restrict__ offb, const float* __restrict__ weight)
{
    __shared__ __align__(16) float ws2[9 * NC * 10 * 2];  // 46080 B
    __shared__ float ts[NC * 129];                        // 33024 B
    int t = threadIdx.x;
    int h = blockIdx.x, b = blockIdx.y;
    int bid = b * NH + h;

    // ---- weight prep chunk (72 per block) + ctr reset ----
    if (bid == 0 && t == 0) g_ctr = 0u;
    if (t < 72) {
        int idx = bid * 72 + t;
        int o = idx / NCK;
        int r = idx - o * NCK;
        int c = r / 9;
        int k = r - c * 9;
        float v = weight[idx];
        __nv_bfloat16 hb = __float2bfloat16(v);
        __nv_bfloat16 lb = __float2bfloat16(v - __bfloat162float(hb));
        int i16 = o * 584 + k * 64 + c;
        g_wimg[i16] = *(unsigned short*)&hb;
        g_wimg[37376 + i16] = *(unsigned short*)&lb;
    }

    if (t < 128) {
        // ===== offsets conv (threads 0-127, barrier 1) =====
        for (int i = t; i < 9 * NC * 10 * 2; i += 128) ws2[i] = 0.f;
        bar_sync(1, 128);
        for (int i = t; i < NOFF * NC * 9; i += 128) {
            int kk = i / (NC * 9);
            int rem = i - kk * (NC * 9);
            int c = rem / 9;
            int tap = rem - c * 9;
            ws2[((tap * NC + c) * 10 + (kk >> 1)) * 2 + (kk & 1)] = offw[i];
        }
        int w = t;
        unsigned long long acc[9];
#pragma unroll
        for (int j = 0; j < 9; j++)
            acc[j] = pack2(__ldg(&offb[2 * j]), __ldg(&offb[2 * j + 1]));
        bar_sync(1, 128);
        bool ok9[9]; int idx9[9];
#pragma unroll
        for (int dh = 0; dh < 3; dh++)
#pragma unroll
            for (int dw = 0; dw < 3; dw++) {
                int hh = h + dh - 1, ww2 = w + dw - 1;
                ok9[dh * 3 + dw] = (hh >= 0 && hh < NH && ww2 >= 0 && ww2 < NW);
                idx9[dh * 3 + dw] = hh * NW + ww2;
            }
        const float* xb = x + (size_t)b * NC * HWSZ;
        for (int c = 0; c < NC; c++) {
            const float* xc = xb + c * HWSZ;
            float v[9];
#pragma unroll
            for (int k = 0; k < 9; k++) v[k] = ok9[k] ? __ldg(&xc[idx9[k]]) : 0.f;
#pragma unroll
            for (int tap = 0; tap < 9; tap++) {
                unsigned long long vd = dup2(v[tap]);
                const ulonglong2* wq = (const ulonglong2*)&ws2[(tap * NC + c) * 20];
                ulonglong2 q0 = wq[0], q1 = wq[1], q2 = wq[2], q3 = wq[3], q4 = wq[4];
                fma2(acc[0], vd, q0.x); fma2(acc[1], vd, q0.y);
                fma2(acc[2], vd, q1.x); fma2(acc[3], vd, q1.y);
                fma2(acc[4], vd, q2.x); fma2(acc[5], vd, q2.y);
                fma2(acc[6], vd, q3.x); fma2(acc[7], vd, q3.y);
                fma2(acc[8], vd, q4.x);
            }
        }
#pragma unroll
        for (int j = 0; j < 9; j++) {
            float lo, hi; unpack2(acc[j], lo, hi);
            g_offsets[((b * NOFF + 2 * j) * NH + h) * NW + w] = lo;
            g_offsets[((b * NOFF + 2 * j + 1) * NH + h) * NW + w] = hi;
        }
    } else {
        // ===== NHWC transpose (threads 128-255, barrier 2) =====
        int t2 = t - 128;
        for (int i = t2; i < NC * NW; i += 128) {
            int c = i >> 7, w2 = i & 127;
            ts[c * 129 + w2] = x[((size_t)(b * NC + c) * NH + h) * NW + w2];
        }
        bar_sync(2, 128);
        for (int i = t2; i < NC * NW; i += 128) {
            int w2 = i >> 6, c = i & 63;
            g_xt[(((size_t)(b * NH + h) * NW) + w2) * NC + c] = ts[c * 129 + w2];
        }
    }
}

// ---------------------------------------------------------------------------
// Kernel 2: HMMA deform. EIGHT independent 128-thread pipelines per block.
// 1024 thr; pipeline p = warps p*4..p*4+3; tile = 16-px eighth-row
// (4096 tiles, dynamic stealing). Warp: m=16 px (whole tile), n-quarter=wl*16.
// SMEM: B 149504 | A 8 pipes x 2 slots x 4608 | prm 8x768 | ctl 256 = 229632.
// ---------------------------------------------------------------------------
#define SM_A 149504
#define SM_PRM 223232
#define SM_CTL 229376
#define SMEM_SZ 229632

__global__ __launch_bounds__(1024, 1) void deform_kernel(
    const float* __restrict__ xt, const float* __restrict__ bias,
    float* __restrict__ out)
{
    extern __shared__ __align__(16) char sm[];
    uint32_t sb = smem_u32(sm);
    int t = threadIdx.x, l = t & 31, wi = t >> 5;
    int p = wi >> 2;               // pipeline 0..7
    int wl = wi & 3;               // warp in pipeline
    int tl = t & 127;              // thread in pipeline
    int barid = 1 + p;             // ids 1..8
    int nq = wl * 16;              // n-quarter

    {   // load B images once (all threads)
        const float4* src = (const float4*)g_wimg;
        float4* dst = (float4*)sm;
        for (int i = t; i < 9344; i += 1024) dst[i] = src[i];
    }
    __syncthreads();

    uint32_t a_lane = (uint32_t)((l & 15) * 72 + ((l >> 4) << 3));
    uint32_t b_lane = (uint32_t)((nq + (l & 7) + ((l >> 4) << 3)) * 584 + (l & 8));

    char* aregion = sm + SM_A + p * 9216;                     // 2 slots x 4608
    float4* prmF = (float4*)(sm + SM_PRM + p * 768);          // [2][16]
    ushort4* prmI = (ushort4*)(sm + SM_PRM + p * 768 + 512);  // [2][16]
    unsigned* ctl = (unsigned*)(sm + SM_CTL) + p * 8;

    for (;;) {
        if (tl == 0) ctl[0] = atomicAdd(&g_ctr, 1u);
        bar_sync(barid, 128);      // publish tile; A/prm free from prev epilogue
        unsigned tile = ctl[0];
        if (tile >= 4096u) break;
        int b = tile >> 10;
        int h = (tile >> 3) & 127;
        int pxg0 = (tile & 7) << 4;
        const float* xb = xt + (size_t)b * HWSZ * NC;

        float acc[2][4];
#pragma unroll
        for (int i = 0; i < 2; i++)
#pragma unroll
            for (int j = 0; j < 4; j++) acc[i][j] = 0.f;

        auto prmc = [&](int tap, int s) {
            if (tl < 16) {
                int px = tl;
                int pxg = pxg0 + px;
                int kh = tap / 3, kw = tap - 3 * kh;
                float offh = __ldg(&g_offsets[((b * NOFF + tap) * NH + h) * NW + pxg]);
                float offw_ = __ldg(&g_offsets[((b * NOFF + 9 + tap) * NH + h) * NW + pxg]);
                float ph = (float)kh + offh + (float)h + 1.f;
                float pw = (float)kw + offw_ + (float)pxg + 1.f;
                ph = fminf(fmaxf(ph, 0.f), 129.f);
                pw = fminf(fmaxf(pw, 0.f), 129.f);
                int h0 = (int)floorf(ph), w0 = (int)floorf(pw);
                int h1 = min(h0 + 1, 129), w1 = min(w0 + 1, 129);
                float wh1 = ph - (float)h0, wh0 = (float)h1 - ph;
                float ww1 = pw - (float)w0, ww0 = (float)w1 - pw;
                int ha = h0 - 1, hb2 = h1 - 1, wa = w0 - 1, wb2 = w1 - 1;
                float fh0 = ((unsigned)ha < 128u) ? wh0 : 0.f;
                float fh1 = ((unsigned)hb2 < 128u) ? wh1 : 0.f;
                float fw0 = ((unsigned)wa < 128u) ? ww0 : 0.f;
                float fw1 = ((unsigned)wb2 < 128u) ? ww1 : 0.f;
                int cha = min(max(ha, 0), 127), chb = min(max(hb2, 0), 127);
                int cwa = min(max(wa, 0), 127), cwb = min(max(wb2, 0), 127);
                prmF[s * 16 + px] = make_float4(fh0 * fw0, fh0 * fw1,
                                                fh1 * fw0, fh1 * fw1);
                ushort4 ii;
                ii.x = (unsigned short)(cha * NW + cwa);
                ii.y = (unsigned short)(cha * NW + cwb);
                ii.z = (unsigned short)(chb * NW + cwa);
                ii.w = (unsigned short)(chb * NW + cwb);
                prmI[s * 16 + px] = ii;
            }
        };

        auto gather = [&](int s) {
            char* aslot = aregion + s * 4608;
#pragma unroll
            for (int it = 0; it < 4; it++) {
                int px = it * 4 + wl;
                float4 f = prmF[s * 16 + px];
                ushort4 ii = prmI[s * 16 + px];
                unsigned long long c00 = ((const unsigned long long*)(xb + (size_t)ii.x * NC))[l];
                unsigned long long c01 = ((const unsigned long long*)(xb + (size_t)ii.y * NC))[l];
                unsigned long long c10 = ((const unsigned long long*)(xb + (size_t)ii.z * NC))[l];
                unsigned long long c11 = ((const unsigned long long*)(xb + (size_t)ii.w * NC))[l];
                unsigned long long v = 0ull;
                fma2(v, c00, dup2(f.x));
                fma2(v, c01, dup2(f.y));
                fma2(v, c10, dup2(f.z));
                fma2(v, c11, dup2(f.w));
                float v0, v1; unpack2(v, v0, v1);
                uint32_t hb = cvtbf2(v0, v1);
                float hf0 = __uint_as_float(hb << 16);
                float hf1 = __uint_as_float(hb & 0xFFFF0000u);
                uint32_t lb = cvtbf2(v0 - hf0, v1 - hf1);
                uint32_t off = (uint32_t)(px * 144 + l * 4);
                *(uint32_t*)(aslot + off) = hb;
                *(uint32_t*)(aslot + 2304 + off) = lb;
            }
        };

        prmc(0, 0);
        bar_sync(barid, 128);
        prmc(1, 1);
        gather(0);
        bar_sync(barid, 128);

#pragma unroll 1
        for (int tap = 0; tap < 9; tap++) {
            int s = tap & 1;
            if (tap < 8) gather((tap + 1) & 1);

            uint32_t abase = sb + SM_A + (uint32_t)(p * 9216 + s * 4608);
#pragma unroll
            for (int ks = 0; ks < 4; ks++) {
                uint32_t ah[4], al[4], bh[4], bl[4];
                uint32_t aoff = abase + (a_lane + ks * 16) * 2;
                ldsm4(ah, aoff);
                ldsm4(al, aoff + 2304);
                uint32_t boff = sb + (b_lane + (uint32_t)(tap * 64 + ks * 16)) * 2;
                ldsm4(bh, boff);
                ldsm4(bl, boff + 74752);
#pragma unroll
                for (int nt = 0; nt < 2; nt++) {
                    mma16816(acc[nt], ah, bh[nt * 2], bh[nt * 2 + 1]);
                    mma16816(acc[nt], ah, bl[nt * 2], bl[nt * 2 + 1]);
                    mma16816(acc[nt], al, bh[nt * 2], bh[nt * 2 + 1]);
                }
            }
            if (tap < 7) prmc(tap + 2, tap & 1);
            bar_sync(barid, 128);
        }

        // ---- epilogue: stage to Cs[o][px16] (reuse A region), coalesced out ----
        float* Cs = (float*)aregion;   // 64 o x 20 stride = 5120 B (< 9216)
        int g = l >> 2, cpair = (l & 3) * 2;
#pragma unroll
        for (int nt = 0; nt < 2; nt++) {
            int o = nq + nt * 8 + cpair;
            Cs[o * 20 + g] = acc[nt][0];
            Cs[(o + 1) * 20 + g] = acc[nt][1];
            Cs[o * 20 + 8 + g] = acc[nt][2];
            Cs[(o + 1) * 20 + 8 + g] = acc[nt][3];
        }
        bar_sync(barid, 128);
#pragma unroll
        for (int oo = 0; oo < 8; oo++) {
            int o = wl * 16 + oo * 2 + (l >> 4);
            int px = l & 15;
            float bs = __ldg(&bias[o]);
            float v = Cs[o * 20 + px] + bs;
            out[(((size_t)b * NO + o) * NH + h) * NW + pxg0 + px] = v;
        }
    }
}

// ---------------------------------------------------------------------------
extern "C" void kernel_launch(void* const* d_in, const int* in_sizes, int n_in,
                              void* d_out, int out_size) {
    const float* x      = (const float*)d_in[0];
    const float* weight = (const float*)d_in[1];
    const float* bias   = (const float*)d_in[2];
    const float* offw   = (const float*)d_in[3];
    const float* offb   = (const float*)d_in[4];
    float* out = (float*)d_out;
    (void)in_sizes; (void)n_in; (void)out_size;

    cudaFuncSetAttribute(deform_kernel,
                         cudaFuncAttributeMaxDynamicSharedMemorySize, SMEM_SZ);

    prep_kernel<<<dim3(NH, NB), 256>>>(x, offw, offb, weight);

    float* xt;
    cudaGetSymbolAddress((void**)&xt, g_xt);
    deform_kernel<<<152, 1024, SMEM_SZ>>>(xt, bias, out);
}